// round 7
// baseline (speedup 1.0000x reference)
#include <cuda_runtime.h>
#include <cuda_fp16.h>

#define NMAX 50000
#define EMAX 800000
#define GROW 512   // 32 h * 16 o
#define NODES_PER_BLOCK 64

// Scratch (static device globals -- no runtime allocation)
__device__ __align__(16) __half g_half[(size_t)NMAX * GROW];  // ~51.2 MB, permuted fp16
__device__ __align__(16) float w2p[16 * GROW];                // permuted fp32 w2
__device__ float xb_buf[NMAX * 16];
__device__ float sum_buf[NMAX * 16];
__device__ int   deg_src[NMAX];
__device__ int   deg_dst[NMAX];
__device__ int   base_src[NMAX];
__device__ int   cursor_src[NMAX];
__device__ int2  ed_pair[EMAX];      // (src, dst)
__device__ int2  sorted_ed[EMAX];    // (eid, dst), grouped by src
__device__ int   idx_is64;

// ---------------------------------------------------------------------------
// Detect edge_index dtype (1 warp, ballot). int64 buffers (values < 2^31,
// little-endian) have zero in every odd 32-bit word.
// ---------------------------------------------------------------------------
__global__ void detect_idx_kernel(const int* __restrict__ raw) {
    int t = threadIdx.x;
    int v = raw[1 + 2 * t];
    unsigned m = __ballot_sync(0xffffffffu, v != 0);
    if (t == 0) idx_is64 = (m == 0u);
}

// ---------------------------------------------------------------------------
// Zero accumulators / counters.
// ---------------------------------------------------------------------------
__global__ void zero_kernel(int N) {
    int i = blockIdx.x * blockDim.x + threadIdx.x;
    if (i < N * 16) sum_buf[i] = 0.f;
    if (i < N) { deg_src[i] = 0; deg_dst[i] = 0; cursor_src[i] = 0; }
}

// ---------------------------------------------------------------------------
// Decode edge_index into packed int2 (src, dst) AND both degree histograms.
// ---------------------------------------------------------------------------
__global__ void decode_hist_kernel(const void* __restrict__ raw, int E) {
    int e = blockIdx.x * blockDim.x + threadIdx.x;
    if (e >= E) return;
    int s, d;
    if (idx_is64) {
        s = (int)((const long long*)raw)[e];
        d = (int)((const long long*)raw)[E + e];
    } else {
        s = ((const int*)raw)[e];
        d = ((const int*)raw)[E + e];
    }
    ed_pair[e] = make_int2(s, d);
    atomicAdd(&deg_src[s], 1);
    atomicAdd(&deg_dst[d], 1);
}

// ---------------------------------------------------------------------------
// Exclusive scan over deg_src -> base_src. Single block of 1024 threads.
// ---------------------------------------------------------------------------
__global__ void scan_kernel(int N) {
    __shared__ int s[1024];
    int t = threadIdx.x;
    int chunk = (N + 1023) / 1024;
    int lo = t * chunk;
    int hi = min(lo + chunk, N);
    int sum = 0;
    for (int n = lo; n < hi; n++) sum += deg_src[n];
    s[t] = sum;
    __syncthreads();
    for (int off = 1; off < 1024; off <<= 1) {
        int other = (t >= off) ? s[t - off] : 0;
        __syncthreads();
        s[t] += other;
        __syncthreads();
    }
    int run = s[t] - sum;   // exclusive prefix of this chunk
    for (int n = lo; n < hi; n++) { base_src[n] = run; run += deg_src[n]; }
}

// ---------------------------------------------------------------------------
// Scatter (eid, dst) into src-grouped order.
// ---------------------------------------------------------------------------
__global__ void scatter_kernel(int E) {
    int e = blockIdx.x * blockDim.x + threadIdx.x;
    if (e >= E) return;
    int2 sd = ed_pair[e];
    int p = base_src[sd.x] + atomicAdd(&cursor_src[sd.x], 1);
    sorted_ed[p] = make_int2(e, sd.y);
}

// ---------------------------------------------------------------------------
// Permute w2 once:  w2p[i*512 + pos] = w2[h*256 + i*16 + o]
// where pos(h,o) = ((h&15)>>3)*256 + ((h>>4)*16 + o)*8 + (h&7).
// ---------------------------------------------------------------------------
__global__ void w2_perm_kernel(const float* __restrict__ w2) {
    int idx = blockIdx.x * blockDim.x + threadIdx.x;
    if (idx >= 16 * GROW) return;
    int i   = idx >> 9;
    int pos = idx & 511;
    int j  = pos >> 8;
    int q  = (pos >> 3) & 31;
    int hb = q >> 4;
    int o  = q & 15;
    int p  = pos & 7;
    int h  = hb * 16 + j * 8 + p;
    w2p[idx] = w2[h * 256 + i * 16 + o];
}

// ---------------------------------------------------------------------------
// Per-node precompute: block of 128 threads handles 64 nodes.
// w2p staged in smem. Thread t owns 4 CONTIGUOUS permuted outputs ->
// one coalesced 8B fp16 store per node. fp32 math.
// ---------------------------------------------------------------------------
__global__ void node_pre_kernel(const float* __restrict__ x,
                                const float* __restrict__ b2,
                                int N) {
    __shared__ float w2s[16 * GROW];            // 32 KB
    __shared__ float xs[NODES_PER_BLOCK * 16];  // 4 KB
    __shared__ float b2s[256];                  // 1 KB
    int t = threadIdx.x;                        // 0..127

    for (int j = t; j < 16 * GROW / 4; j += 128)
        reinterpret_cast<float4*>(w2s)[j] = reinterpret_cast<const float4*>(w2p)[j];
    for (int j = t; j < 256; j += 128) b2s[j] = b2[j];

    int nbase = blockIdx.x * NODES_PER_BLOCK;
    int ncnt  = min(NODES_PER_BLOCK, N - nbase);
    for (int j = t; j < ncnt * 16; j += 128) xs[j] = x[nbase * 16 + j];
    __syncthreads();

    for (int ln = 0; ln < ncnt; ln++) {
        int n = nbase + ln;
        const float4* xr = reinterpret_cast<const float4*>(xs + ln * 16);
        float4 xa = xr[0], xbv = xr[1], xc = xr[2], xd = xr[3];

        float4 acc = make_float4(0.f, 0.f, 0.f, 0.f);
#pragma unroll
        for (int i = 0; i < 16; i++) {
            float xi;
            switch (i >> 2) {
                case 0: xi = (i & 3) == 0 ? xa.x : (i & 3) == 1 ? xa.y : (i & 3) == 2 ? xa.z : xa.w; break;
                case 1: xi = (i & 3) == 0 ? xbv.x : (i & 3) == 1 ? xbv.y : (i & 3) == 2 ? xbv.z : xbv.w; break;
                case 2: xi = (i & 3) == 0 ? xc.x : (i & 3) == 1 ? xc.y : (i & 3) == 2 ? xc.z : xc.w; break;
                default: xi = (i & 3) == 0 ? xd.x : (i & 3) == 1 ? xd.y : (i & 3) == 2 ? xd.z : xd.w; break;
            }
            float4 w = reinterpret_cast<const float4*>(w2s + i * GROW)[t];
            acc.x = fmaf(xi, w.x, acc.x);
            acc.y = fmaf(xi, w.y, acc.y);
            acc.z = fmaf(xi, w.z, acc.z);
            acc.w = fmaf(xi, w.w, acc.w);
        }

        __half2 h0 = __floats2half2_rn(acc.x, acc.y);
        __half2 h1 = __floats2half2_rn(acc.z, acc.w);
        uint2 pk;
        pk.x = *reinterpret_cast<unsigned*>(&h0);
        pk.y = *reinterpret_cast<unsigned*>(&h1);
        *reinterpret_cast<uint2*>(g_half + (size_t)n * GROW + t * 4) = pk;

        if (t < 16) {
            const float* xrs = xs + ln * 16;
            float a = 0.f;
#pragma unroll
            for (int i = 0; i < 16; i++) a = fmaf(xrs[i], b2s[i * 16 + t], a);
            xb_buf[n * 16 + t] = a;
        }
    }
}

// ---------------------------------------------------------------------------
// Per-edge body for the src-grouped kernel. g row already in fp32 registers.
// ---------------------------------------------------------------------------
__device__ __forceinline__ void do_edge_src(int2 ed, int lane,
                                            const float* __restrict__ ea,
                                            const float* __restrict__ w1r,
                                            float b1r,
                                            const float* __restrict__ g,
                                            float xbv) {
    const float4* ea4 = reinterpret_cast<const float4*>(ea + (size_t)ed.x * 16);
    float4 e0 = ea4[0], e1 = ea4[1], e2 = ea4[2], e3 = ea4[3];

    // layer 1: lane l owns hidden unit l
    float a0 = b1r, a1 = 0.f;
    a0 = fmaf(e0.x, w1r[0],  a0);  a1 = fmaf(e0.y, w1r[1],  a1);
    a0 = fmaf(e0.z, w1r[2],  a0);  a1 = fmaf(e0.w, w1r[3],  a1);
    a0 = fmaf(e1.x, w1r[4],  a0);  a1 = fmaf(e1.y, w1r[5],  a1);
    a0 = fmaf(e1.z, w1r[6],  a0);  a1 = fmaf(e1.w, w1r[7],  a1);
    a0 = fmaf(e2.x, w1r[8],  a0);  a1 = fmaf(e2.y, w1r[9],  a1);
    a0 = fmaf(e2.z, w1r[10], a0);  a1 = fmaf(e2.w, w1r[11], a1);
    a0 = fmaf(e3.x, w1r[12], a0);  a1 = fmaf(e3.y, w1r[13], a1);
    a0 = fmaf(e3.z, w1r[14], a0);  a1 = fmaf(e3.w, w1r[15], a1);
    float h = fmaxf(a0 + a1, 0.f);

    // contraction: lane l covers (o=l&15, hb=l>>4); g[j*8+p] is for
    // hidden unit (l&16) + 8j + p.  h fetched via 16 shfl broadcasts.
    int b = lane & 16;
    float p0 = 0.f, p1 = 0.f, p2 = 0.f, p3 = 0.f;
#pragma unroll
    for (int j = 0; j < 2; j++) {
        int bb = b + 8 * j;
        p0 = fmaf(__shfl_sync(0xffffffffu, h, bb + 0), g[j * 8 + 0], p0);
        p1 = fmaf(__shfl_sync(0xffffffffu, h, bb + 1), g[j * 8 + 1], p1);
        p2 = fmaf(__shfl_sync(0xffffffffu, h, bb + 2), g[j * 8 + 2], p2);
        p3 = fmaf(__shfl_sync(0xffffffffu, h, bb + 3), g[j * 8 + 3], p3);
        p0 = fmaf(__shfl_sync(0xffffffffu, h, bb + 4), g[j * 8 + 4], p0);
        p1 = fmaf(__shfl_sync(0xffffffffu, h, bb + 5), g[j * 8 + 5], p1);
        p2 = fmaf(__shfl_sync(0xffffffffu, h, bb + 6), g[j * 8 + 6], p2);
        p3 = fmaf(__shfl_sync(0xffffffffu, h, bb + 7), g[j * 8 + 7], p3);
    }
    float partial = (p0 + p1) + (p2 + p3);
    partial += __shfl_xor_sync(0xffffffffu, partial, 16);

    if (lane < 16)
        atomicAdd(&sum_buf[ed.y * 16 + lane], partial + xbv);
}

// ---------------------------------------------------------------------------
// Main kernel: one warp per SOURCE node (grid-stride). g row loaded once
// (2 LDG.128 fp16), converted once to 16 fp32 regs; per edge only
// 1 int2 load + 4 uniform ea loads + RED.
// ---------------------------------------------------------------------------
__global__ void src_edge_kernel(const float* __restrict__ ea,
                                const float* __restrict__ w1,
                                const float* __restrict__ b1,
                                int N) {
    int lane = threadIdx.x & 31;
    int gwarp = (blockIdx.x * (blockDim.x >> 5)) + (threadIdx.x >> 5);
    int nwarps = gridDim.x * (blockDim.x >> 5);

    float w1r[16];
#pragma unroll
    for (int i = 0; i < 16; i++) w1r[i] = w1[i * 32 + lane];
    float b1r = b1[lane];

    for (int n = gwarp; n < N; n += nwarps) {
        int deg = deg_src[n];
        if (deg == 0) continue;
        int base = base_src[n];

        // load + convert g row once
        const uint4* G16 = reinterpret_cast<const uint4*>(
            g_half + (size_t)n * GROW) + lane;
        uint4 ga = G16[0], gb = G16[32];
        float g[16];
        {
            const __half2* ha = reinterpret_cast<const __half2*>(&ga);
            const __half2* hb = reinterpret_cast<const __half2*>(&gb);
#pragma unroll
            for (int m = 0; m < 4; m++) {
                float2 fa = __half22float2(ha[m]);
                float2 fb = __half22float2(hb[m]);
                g[2 * m]     = fa.x;  g[2 * m + 1]     = fa.y;
                g[8 + 2 * m] = fb.x;  g[8 + 2 * m + 1] = fb.y;
            }
        }
        float xbv = xb_buf[n * 16 + (lane & 15)];

        int p = 0;
        for (; p + 2 <= deg; p += 2) {
            int2 ed0 = sorted_ed[base + p];
            int2 ed1 = sorted_ed[base + p + 1];
            do_edge_src(ed0, lane, ea, w1r, b1r, g, xbv);
            do_edge_src(ed1, lane, ea, w1r, b1r, g, xbv);
        }
        if (p < deg) {
            int2 ed = sorted_ed[base + p];
            do_edge_src(ed, lane, ea, w1r, b1r, g, xbv);
        }
    }
}

// ---------------------------------------------------------------------------
// Finalize: out[n][o] = sum[n][o]/max(indeg,1) + x[n]@root[:,o] + bias[o]
// ---------------------------------------------------------------------------
__global__ void finalize_kernel(const float* __restrict__ x,
                                const float* __restrict__ root,
                                const float* __restrict__ bias,
                                float* __restrict__ out, int N) {
    int idx = blockIdx.x * blockDim.x + threadIdx.x;
    if (idx >= N * 16) return;
    int n = idx >> 4;
    int o = idx & 15;
    float c = (float)deg_dst[n];
    float a = sum_buf[idx] / fmaxf(c, 1.0f);
    float r = 0.f;
#pragma unroll
    for (int i = 0; i < 16; i++) r = fmaf(x[n * 16 + i], root[i * 16 + o], r);
    out[idx] = a + r + bias[o];
}

extern "C" void kernel_launch(void* const* d_in, const int* in_sizes, int n_in,
                              void* d_out, int out_size) {
    const float* x    = (const float*)d_in[0];
    const void*  ei   = d_in[1];
    const float* ea   = (const float*)d_in[2];
    const float* w1   = (const float*)d_in[3];
    const float* b1   = (const float*)d_in[4];
    const float* w2   = (const float*)d_in[5];
    const float* b2   = (const float*)d_in[6];
    const float* root = (const float*)d_in[7];
    const float* bias = (const float*)d_in[8];
    float*       out  = (float*)d_out;

    int N = in_sizes[0] / 16;
    int E = in_sizes[2] / 16;

    zero_kernel<<<(N * 16 + 255) / 256, 256>>>(N);
    detect_idx_kernel<<<1, 32>>>((const int*)ei);
    w2_perm_kernel<<<(16 * GROW + 255) / 256, 256>>>(w2);
    decode_hist_kernel<<<(E + 255) / 256, 256>>>(ei, E);
    scan_kernel<<<1, 1024>>>(N);
    scatter_kernel<<<(E + 255) / 256, 256>>>(E);

    node_pre_kernel<<<(N + NODES_PER_BLOCK - 1) / NODES_PER_BLOCK, 128>>>(x, b2, N);

    src_edge_kernel<<<(N + 7) / 8, 256>>>(ea, w1, b1, N);

    finalize_kernel<<<(N * 16 + 255) / 256, 256>>>(x, root, bias, out, N);
}

// round 8
// speedup vs baseline: 1.5527x; 1.5527x over previous
#include <cuda_runtime.h>
#include <cuda_fp16.h>

#define NMAX 50000
#define EMAX 800000
#define GROW 512   // 32 h * 16 o
#define NODES_PER_BLOCK 64

// Scratch (static device globals -- no runtime allocation)
__device__ __align__(16) __half g_half[(size_t)NMAX * GROW];  // ~51.2 MB, permuted fp16
__device__ __align__(16) float w2p[16 * GROW];                // permuted fp32 w2
__device__ __align__(16) float xb_buf[NMAX * 16];
__device__ __align__(16) float sum_buf[NMAX * 16];
__device__ int   deg_dst[NMAX];
__device__ int2  ed_pair[EMAX];      // (src, dst)
__device__ int   idx_is64;

// ---------------------------------------------------------------------------
// Fused setup: zero sum/deg, permute w2, detect edge_index dtype.
// Grid covers N*16 threads (= E = 800k here).
// ---------------------------------------------------------------------------
__global__ void setup_kernel(const float* __restrict__ w2,
                             const int* __restrict__ raw_idx, int N) {
    int i = blockIdx.x * blockDim.x + threadIdx.x;
    if (i < N * 16) sum_buf[i] = 0.f;
    if (i < N) deg_dst[i] = 0;

    if (i < 16 * GROW) {
        // w2p[i*512 + pos] = w2[h*256 + i*16 + o],
        // pos(h,o) = ((h&15)>>3)*256 + ((h>>4)*16 + o)*8 + (h&7)
        int ii  = i >> 9;
        int pos = i & 511;
        int j  = pos >> 8;
        int q  = (pos >> 3) & 31;
        int hb = q >> 4;
        int o  = q & 15;
        int p  = pos & 7;
        int h  = hb * 16 + j * 8 + p;
        w2p[i] = w2[h * 256 + ii * 16 + o];
    }

    if (blockIdx.x == 0 && threadIdx.x < 32) {
        int v = raw_idx[1 + 2 * threadIdx.x];
        unsigned m = __ballot_sync(0xffffffffu, v != 0);
        if (threadIdx.x == 0) idx_is64 = (m == 0u);
    }
}

// ---------------------------------------------------------------------------
// Decode edge_index into packed int2 (src, dst) AND build in-degree histogram.
// ---------------------------------------------------------------------------
__global__ void decode_hist_kernel(const void* __restrict__ raw, int E) {
    int e = blockIdx.x * blockDim.x + threadIdx.x;
    if (e >= E) return;
    int s, d;
    if (idx_is64) {
        s = (int)((const long long*)raw)[e];
        d = (int)((const long long*)raw)[E + e];
    } else {
        s = ((const int*)raw)[e];
        d = ((const int*)raw)[E + e];
    }
    ed_pair[e] = make_int2(s, d);
    atomicAdd(&deg_dst[d], 1);
}

// ---------------------------------------------------------------------------
// Per-node precompute: block of 128 threads handles 64 nodes.
// w2p staged in smem. Thread t owns 4 CONTIGUOUS permuted outputs ->
// one coalesced 8B fp16 store per node. fp32 math.
// ---------------------------------------------------------------------------
__global__ void node_pre_kernel(const float* __restrict__ x,
                                const float* __restrict__ b2,
                                int N) {
    __shared__ float w2s[16 * GROW];            // 32 KB
    __shared__ float xs[NODES_PER_BLOCK * 16];  // 4 KB
    __shared__ float b2s[256];                  // 1 KB
    int t = threadIdx.x;                        // 0..127

    for (int j = t; j < 16 * GROW / 4; j += 128)
        reinterpret_cast<float4*>(w2s)[j] = reinterpret_cast<const float4*>(w2p)[j];
    for (int j = t; j < 256; j += 128) b2s[j] = b2[j];

    int nbase = blockIdx.x * NODES_PER_BLOCK;
    int ncnt  = min(NODES_PER_BLOCK, N - nbase);
    for (int j = t; j < ncnt * 16; j += 128) xs[j] = x[nbase * 16 + j];
    __syncthreads();

    for (int ln = 0; ln < ncnt; ln++) {
        int n = nbase + ln;
        const float4* xr = reinterpret_cast<const float4*>(xs + ln * 16);
        float4 xa = xr[0], xbv = xr[1], xc = xr[2], xd = xr[3];

        float4 acc = make_float4(0.f, 0.f, 0.f, 0.f);
#pragma unroll
        for (int i = 0; i < 16; i++) {
            float xi;
            switch (i >> 2) {
                case 0: xi = (i & 3) == 0 ? xa.x : (i & 3) == 1 ? xa.y : (i & 3) == 2 ? xa.z : xa.w; break;
                case 1: xi = (i & 3) == 0 ? xbv.x : (i & 3) == 1 ? xbv.y : (i & 3) == 2 ? xbv.z : xbv.w; break;
                case 2: xi = (i & 3) == 0 ? xc.x : (i & 3) == 1 ? xc.y : (i & 3) == 2 ? xc.z : xc.w; break;
                default: xi = (i & 3) == 0 ? xd.x : (i & 3) == 1 ? xd.y : (i & 3) == 2 ? xd.z : xd.w; break;
            }
            float4 w = reinterpret_cast<const float4*>(w2s + i * GROW)[t];
            acc.x = fmaf(xi, w.x, acc.x);
            acc.y = fmaf(xi, w.y, acc.y);
            acc.z = fmaf(xi, w.z, acc.z);
            acc.w = fmaf(xi, w.w, acc.w);
        }

        __half2 h0 = __floats2half2_rn(acc.x, acc.y);
        __half2 h1 = __floats2half2_rn(acc.z, acc.w);
        uint2 pk;
        pk.x = *reinterpret_cast<unsigned*>(&h0);
        pk.y = *reinterpret_cast<unsigned*>(&h1);
        *reinterpret_cast<uint2*>(g_half + (size_t)n * GROW + t * 4) = pk;

        if (t < 16) {
            const float* xrs = xs + ln * 16;
            float a = 0.f;
#pragma unroll
            for (int i = 0; i < 16; i++) a = fmaf(xrs[i], b2s[i * 16 + t], a);
            xb_buf[n * 16 + t] = a;
        }
    }
}

// ---------------------------------------------------------------------------
// One-edge body. h pairs packed into half2 -> 8 contraction shfls; message
// scatter via red.global.v4.f32.add from 4 lanes (was 16 scalar REDs).
// ---------------------------------------------------------------------------
__device__ __forceinline__ void do_edge(int e, int lane,
                                        const float* __restrict__ ea,
                                        const float* __restrict__ w1r,
                                        float b1r) {
    int2 sd = ed_pair[e];                       // uniform across warp
    const float4* ea4 = reinterpret_cast<const float4*>(ea + (size_t)e * 16);
    float4 e0 = ea4[0], e1 = ea4[1], e2 = ea4[2], e3 = ea4[3];

    // layer 1: all-register FMA (two chains)
    float a0 = b1r, a1 = 0.f;
    a0 = fmaf(e0.x, w1r[0],  a0);  a1 = fmaf(e0.y, w1r[1],  a1);
    a0 = fmaf(e0.z, w1r[2],  a0);  a1 = fmaf(e0.w, w1r[3],  a1);
    a0 = fmaf(e1.x, w1r[4],  a0);  a1 = fmaf(e1.y, w1r[5],  a1);
    a0 = fmaf(e1.z, w1r[6],  a0);  a1 = fmaf(e1.w, w1r[7],  a1);
    a0 = fmaf(e2.x, w1r[8],  a0);  a1 = fmaf(e2.y, w1r[9],  a1);
    a0 = fmaf(e2.z, w1r[10], a0);  a1 = fmaf(e2.w, w1r[11], a1);
    a0 = fmaf(e3.x, w1r[12], a0);  a1 = fmaf(e3.y, w1r[13], a1);
    a0 = fmaf(e3.z, w1r[14], a0);  a1 = fmaf(e3.w, w1r[15], a1);
    float h = fmaxf(a0 + a1, 0.f);

    // pack neighbor pair: every lane ends with half2(h[2m], h[2m+1]), m=lane>>1
    float hn = __shfl_xor_sync(0xffffffffu, h, 1);
    float plo = (lane & 1) ? hn : h;
    float phi = (lane & 1) ? h : hn;
    __half2 hp2 = __floats2half2_rn(plo, phi);
    unsigned hpu = *reinterpret_cast<unsigned*>(&hp2);

    // contraction: lane l covers (o=l&15, hb=l>>4); 2 x uint4 = 16 halves
    const uint4* G16 = reinterpret_cast<const uint4*>(
        g_half + (size_t)sd.x * GROW) + lane;
    int hb16 = lane & 16;
    float p0 = 0.f, p1 = 0.f, p2 = 0.f, p3 = 0.f;
#pragma unroll
    for (int j = 0; j < 2; j++) {
        uint4 gv = G16[j * 32];
        const __half2* gp = reinterpret_cast<const __half2*>(&gv);
        int b = hb16 + 8 * j;
        unsigned q0 = __shfl_sync(0xffffffffu, hpu, b + 0);
        unsigned q1 = __shfl_sync(0xffffffffu, hpu, b + 2);
        unsigned q2 = __shfl_sync(0xffffffffu, hpu, b + 4);
        unsigned q3 = __shfl_sync(0xffffffffu, hpu, b + 6);
        float2 h0 = __half22float2(*reinterpret_cast<__half2*>(&q0));
        float2 h1 = __half22float2(*reinterpret_cast<__half2*>(&q1));
        float2 h2 = __half22float2(*reinterpret_cast<__half2*>(&q2));
        float2 h3 = __half22float2(*reinterpret_cast<__half2*>(&q3));
        float2 f0 = __half22float2(gp[0]);
        float2 f1 = __half22float2(gp[1]);
        float2 f2 = __half22float2(gp[2]);
        float2 f3 = __half22float2(gp[3]);
        p0 = fmaf(h0.x, f0.x, p0);  p1 = fmaf(h0.y, f0.y, p1);
        p2 = fmaf(h1.x, f1.x, p2);  p3 = fmaf(h1.y, f1.y, p3);
        p0 = fmaf(h2.x, f2.x, p0);  p1 = fmaf(h2.y, f2.y, p1);
        p2 = fmaf(h3.x, f3.x, p2);  p3 = fmaf(h3.y, f3.y, p3);
    }
    float partial = (p0 + p1) + (p2 + p3);
    partial += __shfl_xor_sync(0xffffffffu, partial, 16);

    // message for o = lane&15 (valid in lanes 0-15)
    float msg = partial + ((lane < 16) ? xb_buf[sd.x * 16 + lane] : 0.f);

    // gather 4 consecutive o's into lanes 0,4,8,12 and issue one RED.128
    float m1 = __shfl_down_sync(0xffffffffu, msg, 1);
    float m2 = __shfl_down_sync(0xffffffffu, msg, 2);
    float m3 = __shfl_down_sync(0xffffffffu, msg, 3);
    if (lane < 16 && (lane & 3) == 0) {
        float* dstp = sum_buf + (size_t)sd.y * 16 + lane;
        asm volatile("red.global.v4.f32.add [%0], {%1, %2, %3, %4};"
                     :: "l"(dstp), "f"(msg), "f"(m1), "f"(m2), "f"(m3)
                     : "memory");
    }
}

// ---------------------------------------------------------------------------
// Edge kernel: persistent warps, TWO independent edges per iteration.
// ---------------------------------------------------------------------------
__global__ void edge_kernel(const float* __restrict__ ea,
                            const float* __restrict__ w1,
                            const float* __restrict__ b1,
                            int E) {
    int lane = threadIdx.x & 31;
    int gwarp = (blockIdx.x * (blockDim.x >> 5)) + (threadIdx.x >> 5);
    int nwarps = gridDim.x * (blockDim.x >> 5);

    float w1r[16];
#pragma unroll
    for (int i = 0; i < 16; i++) w1r[i] = w1[i * 32 + lane];
    float b1r = b1[lane];

    int stride = 2 * nwarps;
    for (int e = gwarp * 2; e < E; e += stride) {
        do_edge(e, lane, ea, w1r, b1r);
        if (e + 1 < E) do_edge(e + 1, lane, ea, w1r, b1r);
    }
}

// ---------------------------------------------------------------------------
// Finalize: out[n][o] = sum[n][o]/max(indeg,1) + x[n]@root[:,o] + bias[o]
// ---------------------------------------------------------------------------
__global__ void finalize_kernel(const float* __restrict__ x,
                                const float* __restrict__ root,
                                const float* __restrict__ bias,
                                float* __restrict__ out, int N) {
    int idx = blockIdx.x * blockDim.x + threadIdx.x;
    if (idx >= N * 16) return;
    int n = idx >> 4;
    int o = idx & 15;
    float c = (float)deg_dst[n];
    float a = sum_buf[idx] / fmaxf(c, 1.0f);
    float r = 0.f;
#pragma unroll
    for (int i = 0; i < 16; i++) r = fmaf(x[n * 16 + i], root[i * 16 + o], r);
    out[idx] = a + r + bias[o];
}

extern "C" void kernel_launch(void* const* d_in, const int* in_sizes, int n_in,
                              void* d_out, int out_size) {
    const float* x    = (const float*)d_in[0];
    const void*  ei   = d_in[1];
    const float* ea   = (const float*)d_in[2];
    const float* w1   = (const float*)d_in[3];
    const float* b1   = (const float*)d_in[4];
    const float* w2   = (const float*)d_in[5];
    const float* b2   = (const float*)d_in[6];
    const float* root = (const float*)d_in[7];
    const float* bias = (const float*)d_in[8];
    float*       out  = (float*)d_out;

    int N = in_sizes[0] / 16;
    int E = in_sizes[2] / 16;

    setup_kernel<<<(N * 16 + 255) / 256, 256>>>(w2, (const int*)ei, N);
    decode_hist_kernel<<<(E + 255) / 256, 256>>>(ei, E);

    node_pre_kernel<<<(N + NODES_PER_BLOCK - 1) / NODES_PER_BLOCK, 128>>>(x, b2, N);

    edge_kernel<<<2048, 256>>>(ea, w1, b1, E);

    finalize_kernel<<<(N * 16 + 255) / 256, 256>>>(x, root, bias, out, N);
}

// round 9
// speedup vs baseline: 1.6940x; 1.0910x over previous
#include <cuda_runtime.h>
#include <cuda_fp16.h>

#define NMAX 50000
#define EMAX 800000
#define GROW 512   // 32 h * 16 o
#define NODES_PER_BLOCK 64

// Scratch (static device globals -- no runtime allocation)
__device__ __align__(16) __half g_half[(size_t)NMAX * GROW];  // ~51.2 MB, permuted fp16
__device__ __align__(16) float w2p[16 * GROW];                // permuted fp32 w2
__device__ __align__(16) float xb_buf[NMAX * 16];
__device__ __align__(16) float sum_buf[NMAX * 16];
__device__ int   deg_dst[NMAX];
__device__ int2  ed_pair[EMAX];      // (src, dst)
__device__ int   idx_is64;

// ---------------------------------------------------------------------------
// Fused setup: zero sum/deg, permute w2, detect edge_index dtype.
// ---------------------------------------------------------------------------
__global__ void setup_kernel(const float* __restrict__ w2,
                             const int* __restrict__ raw_idx, int N) {
    int i = blockIdx.x * blockDim.x + threadIdx.x;
    if (i < N * 16) sum_buf[i] = 0.f;
    if (i < N) deg_dst[i] = 0;

    if (i < 16 * GROW) {
        // w2p[i*512 + pos] = w2[h*256 + i*16 + o],
        // pos(h,o) = ((h&15)>>3)*256 + ((h>>4)*16 + o)*8 + (h&7)
        int ii  = i >> 9;
        int pos = i & 511;
        int j  = pos >> 8;
        int q  = (pos >> 3) & 31;
        int hb = q >> 4;
        int o  = q & 15;
        int p  = pos & 7;
        int h  = hb * 16 + j * 8 + p;
        w2p[i] = w2[h * 256 + ii * 16 + o];
    }

    if (blockIdx.x == 0 && threadIdx.x < 32) {
        int v = raw_idx[1 + 2 * threadIdx.x];
        unsigned m = __ballot_sync(0xffffffffu, v != 0);
        if (threadIdx.x == 0) idx_is64 = (m == 0u);
    }
}

// ---------------------------------------------------------------------------
// Decode edge_index into packed int2 (src, dst) AND build in-degree histogram.
// ---------------------------------------------------------------------------
__global__ void decode_hist_kernel(const void* __restrict__ raw, int E) {
    int e = blockIdx.x * blockDim.x + threadIdx.x;
    if (e >= E) return;
    int s, d;
    if (idx_is64) {
        s = (int)((const long long*)raw)[e];
        d = (int)((const long long*)raw)[E + e];
    } else {
        s = ((const int*)raw)[e];
        d = ((const int*)raw)[E + e];
    }
    ed_pair[e] = make_int2(s, d);
    atomicAdd(&deg_dst[d], 1);
}

// ---------------------------------------------------------------------------
// Per-node precompute: block of 128 threads handles 64 nodes.
// w2p staged in smem. Thread t owns 4 CONTIGUOUS permuted outputs ->
// one coalesced 8B fp16 store per node. fp32 math.
// ---------------------------------------------------------------------------
__global__ void node_pre_kernel(const float* __restrict__ x,
                                const float* __restrict__ b2,
                                int N) {
    __shared__ float w2s[16 * GROW];            // 32 KB
    __shared__ float xs[NODES_PER_BLOCK * 16];  // 4 KB
    __shared__ float b2s[256];                  // 1 KB
    int t = threadIdx.x;                        // 0..127

    for (int j = t; j < 16 * GROW / 4; j += 128)
        reinterpret_cast<float4*>(w2s)[j] = reinterpret_cast<const float4*>(w2p)[j];
    for (int j = t; j < 256; j += 128) b2s[j] = b2[j];

    int nbase = blockIdx.x * NODES_PER_BLOCK;
    int ncnt  = min(NODES_PER_BLOCK, N - nbase);
    for (int j = t; j < ncnt * 16; j += 128) xs[j] = x[nbase * 16 + j];
    __syncthreads();

    for (int ln = 0; ln < ncnt; ln++) {
        int n = nbase + ln;
        const float4* xr = reinterpret_cast<const float4*>(xs + ln * 16);
        float4 xa = xr[0], xbv = xr[1], xc = xr[2], xd = xr[3];

        float4 acc = make_float4(0.f, 0.f, 0.f, 0.f);
#pragma unroll
        for (int i = 0; i < 16; i++) {
            float xi;
            switch (i >> 2) {
                case 0: xi = (i & 3) == 0 ? xa.x : (i & 3) == 1 ? xa.y : (i & 3) == 2 ? xa.z : xa.w; break;
                case 1: xi = (i & 3) == 0 ? xbv.x : (i & 3) == 1 ? xbv.y : (i & 3) == 2 ? xbv.z : xbv.w; break;
                case 2: xi = (i & 3) == 0 ? xc.x : (i & 3) == 1 ? xc.y : (i & 3) == 2 ? xc.z : xc.w; break;
                default: xi = (i & 3) == 0 ? xd.x : (i & 3) == 1 ? xd.y : (i & 3) == 2 ? xd.z : xd.w; break;
            }
            float4 w = reinterpret_cast<const float4*>(w2s + i * GROW)[t];
            acc.x = fmaf(xi, w.x, acc.x);
            acc.y = fmaf(xi, w.y, acc.y);
            acc.z = fmaf(xi, w.z, acc.z);
            acc.w = fmaf(xi, w.w, acc.w);
        }

        __half2 h0 = __floats2half2_rn(acc.x, acc.y);
        __half2 h1 = __floats2half2_rn(acc.z, acc.w);
        uint2 pk;
        pk.x = *reinterpret_cast<unsigned*>(&h0);
        pk.y = *reinterpret_cast<unsigned*>(&h1);
        *reinterpret_cast<uint2*>(g_half + (size_t)n * GROW + t * 4) = pk;

        if (t < 16) {
            const float* xrs = xs + ln * 16;
            float a = 0.f;
#pragma unroll
            for (int i = 0; i < 16; i++) a = fmaf(xrs[i], b2s[i * 16 + t], a);
            xb_buf[n * 16 + t] = a;
        }
    }
}

// ---------------------------------------------------------------------------
// One-edge body. ea float4s consumed immediately (low live-register count);
// h pairs packed into half2 -> 8 contraction shfls; scatter via RED.128.
// ---------------------------------------------------------------------------
__device__ __forceinline__ void do_edge(int e, int lane,
                                        const float* __restrict__ ea,
                                        const float* __restrict__ w1r,
                                        float b1r) {
    int2 sd = ed_pair[e];                       // uniform across warp
    const float4* ea4 = reinterpret_cast<const float4*>(ea + (size_t)e * 16);

    // layer 1: consume each float4 right after load (two chains)
    float a0 = b1r, a1 = 0.f;
    {
        float4 v = ea4[0];
        a0 = fmaf(v.x, w1r[0],  a0);  a1 = fmaf(v.y, w1r[1],  a1);
        a0 = fmaf(v.z, w1r[2],  a0);  a1 = fmaf(v.w, w1r[3],  a1);
    }
    {
        float4 v = ea4[1];
        a0 = fmaf(v.x, w1r[4],  a0);  a1 = fmaf(v.y, w1r[5],  a1);
        a0 = fmaf(v.z, w1r[6],  a0);  a1 = fmaf(v.w, w1r[7],  a1);
    }
    {
        float4 v = ea4[2];
        a0 = fmaf(v.x, w1r[8],  a0);  a1 = fmaf(v.y, w1r[9],  a1);
        a0 = fmaf(v.z, w1r[10], a0);  a1 = fmaf(v.w, w1r[11], a1);
    }
    {
        float4 v = ea4[3];
        a0 = fmaf(v.x, w1r[12], a0);  a1 = fmaf(v.y, w1r[13], a1);
        a0 = fmaf(v.z, w1r[14], a0);  a1 = fmaf(v.w, w1r[15], a1);
    }
    float h = fmaxf(a0 + a1, 0.f);

    // pack neighbor pair: every lane ends with half2(h[2m], h[2m+1]), m=lane>>1
    float hn = __shfl_xor_sync(0xffffffffu, h, 1);
    float plo = (lane & 1) ? hn : h;
    float phi = (lane & 1) ? h : hn;
    __half2 hp2 = __floats2half2_rn(plo, phi);
    unsigned hpu = *reinterpret_cast<unsigned*>(&hp2);

    // contraction: lane l covers (o=l&15, hb=l>>4); 2 x uint4 = 16 halves
    const uint4* G16 = reinterpret_cast<const uint4*>(
        g_half + (size_t)sd.x * GROW) + lane;
    int hb16 = lane & 16;
    float p0 = 0.f, p1 = 0.f, p2 = 0.f, p3 = 0.f;
#pragma unroll
    for (int j = 0; j < 2; j++) {
        uint4 gv = G16[j * 32];
        const __half2* gp = reinterpret_cast<const __half2*>(&gv);
        int b = hb16 + 8 * j;
        unsigned q0 = __shfl_sync(0xffffffffu, hpu, b + 0);
        unsigned q1 = __shfl_sync(0xffffffffu, hpu, b + 2);
        unsigned q2 = __shfl_sync(0xffffffffu, hpu, b + 4);
        unsigned q3 = __shfl_sync(0xffffffffu, hpu, b + 6);
        float2 h0 = __half22float2(*reinterpret_cast<__half2*>(&q0));
        float2 h1 = __half22float2(*reinterpret_cast<__half2*>(&q1));
        float2 h2 = __half22float2(*reinterpret_cast<__half2*>(&q2));
        float2 h3 = __half22float2(*reinterpret_cast<__half2*>(&q3));
        float2 f0 = __half22float2(gp[0]);
        float2 f1 = __half22float2(gp[1]);
        float2 f2 = __half22float2(gp[2]);
        float2 f3 = __half22float2(gp[3]);
        p0 = fmaf(h0.x, f0.x, p0);  p1 = fmaf(h0.y, f0.y, p1);
        p2 = fmaf(h1.x, f1.x, p2);  p3 = fmaf(h1.y, f1.y, p3);
        p0 = fmaf(h2.x, f2.x, p0);  p1 = fmaf(h2.y, f2.y, p1);
        p2 = fmaf(h3.x, f3.x, p2);  p3 = fmaf(h3.y, f3.y, p3);
    }
    float partial = (p0 + p1) + (p2 + p3);
    partial += __shfl_xor_sync(0xffffffffu, partial, 16);

    // message for o = lane&15 (xb load broadcasts across half-warps)
    float msg = partial + xb_buf[sd.x * 16 + (lane & 15)];

    // gather 4 consecutive o's into lanes 0,4,8,12 and issue one RED.128
    float m1 = __shfl_down_sync(0xffffffffu, msg, 1);
    float m2 = __shfl_down_sync(0xffffffffu, msg, 2);
    float m3 = __shfl_down_sync(0xffffffffu, msg, 3);
    if (lane < 16 && (lane & 3) == 0) {
        float* dstp = sum_buf + (size_t)sd.y * 16 + lane;
        asm volatile("red.global.v4.f32.add [%0], {%1, %2, %3, %4};"
                     :: "l"(dstp), "f"(msg), "f"(m1), "f"(m2), "f"(m3)
                     : "memory");
    }
}

// ---------------------------------------------------------------------------
// Edge kernel: persistent warps, TWO independent edges per iteration.
// __launch_bounds__(256, 5): cap 51 regs -> 5 blocks/SM = 40 warps (62.5%).
// ---------------------------------------------------------------------------
__global__ void __launch_bounds__(256, 5)
edge_kernel(const float* __restrict__ ea,
            const float* __restrict__ w1,
            const float* __restrict__ b1,
            int E) {
    int lane = threadIdx.x & 31;
    int gwarp = (blockIdx.x * (blockDim.x >> 5)) + (threadIdx.x >> 5);
    int nwarps = gridDim.x * (blockDim.x >> 5);

    float w1r[16];
#pragma unroll
    for (int i = 0; i < 16; i++) w1r[i] = w1[i * 32 + lane];
    float b1r = b1[lane];

    int stride = 2 * nwarps;
    for (int e = gwarp * 2; e < E; e += stride) {
        do_edge(e, lane, ea, w1r, b1r);
        if (e + 1 < E) do_edge(e + 1, lane, ea, w1r, b1r);
    }
}

// ---------------------------------------------------------------------------
// Finalize: out[n][o] = sum[n][o]/max(indeg,1) + x[n]@root[:,o] + bias[o]
// ---------------------------------------------------------------------------
__global__ void finalize_kernel(const float* __restrict__ x,
                                const float* __restrict__ root,
                                const float* __restrict__ bias,
                                float* __restrict__ out, int N) {
    int idx = blockIdx.x * blockDim.x + threadIdx.x;
    if (idx >= N * 16) return;
    int n = idx >> 4;
    int o = idx & 15;
    float c = (float)deg_dst[n];
    float a = sum_buf[idx] / fmaxf(c, 1.0f);
    float r = 0.f;
#pragma unroll
    for (int i = 0; i < 16; i++) r = fmaf(x[n * 16 + i], root[i * 16 + o], r);
    out[idx] = a + r + bias[o];
}

extern "C" void kernel_launch(void* const* d_in, const int* in_sizes, int n_in,
                              void* d_out, int out_size) {
    const float* x    = (const float*)d_in[0];
    const void*  ei   = d_in[1];
    const float* ea   = (const float*)d_in[2];
    const float* w1   = (const float*)d_in[3];
    const float* b1   = (const float*)d_in[4];
    const float* w2   = (const float*)d_in[5];
    const float* b2   = (const float*)d_in[6];
    const float* root = (const float*)d_in[7];
    const float* bias = (const float*)d_in[8];
    float*       out  = (float*)d_out;

    int N = in_sizes[0] / 16;
    int E = in_sizes[2] / 16;

    setup_kernel<<<(N * 16 + 255) / 256, 256>>>(w2, (const int*)ei, N);
    decode_hist_kernel<<<(E + 255) / 256, 256>>>(ei, E);

    node_pre_kernel<<<(N + NODES_PER_BLOCK - 1) / NODES_PER_BLOCK, 128>>>(x, b2, N);

    edge_kernel<<<2048, 256>>>(ea, w1, b1, E);

    finalize_kernel<<<(N * 16 + 255) / 256, 256>>>(x, root, bias, out, N);
}